// round 6
// baseline (speedup 1.0000x reference)
#include <cuda_runtime.h>
#include <cstdint>

// TPlanesEnc: B=4, N=131072, P=512, F=32.
// d_in[0] = coords  [B, N, 3]   fp32
// d_in[1] = tplanes [3, P, P, F] fp32 (3 x 32 MB)
// d_out   = out     [B, N, 3*F] fp32  (201 MB streaming)
//
// R5: three passes, one plane per pass. Hot texture per pass = 32 MB, fully
// L2-resident -> kills the ~200 MB of texture re-fetch DRAM traffic seen when
// all 3 planes (96 MB) contend with the 201 MB write stream. Warp-per-point,
// lane = channel: 4 coalesced 128B texel loads + 1 coalesced 128B store.

#define PS 512
#define FD 32

__device__ __forceinline__ void stg_streaming(float* p, float v) {
    asm volatile("st.global.cs.f32 [%0], %1;" :: "l"(p), "f"(v) : "memory");
}

template<int PLANE, int UAX, int VAX>
__global__ __launch_bounds__(256, 8)
void tplane_pass(const float* __restrict__ coords,
                 const float* __restrict__ tpl,
                 float* __restrict__ out,
                 int M)
{
    const int gtid = blockIdx.x * blockDim.x + threadIdx.x;
    const int warp = gtid >> 5;
    const int lane = threadIdx.x & 31;
    if (warp >= M) return;

    const float cu = __ldg(&coords[warp * 3 + UAX]);
    const float cv = __ldg(&coords[warp * 3 + VAX]);

    // Texel-space coords with clamp-to-edge (nvdiffrast linear/clamp, no mip)
    float u = (cu * 0.5f + 0.5f) * (float)PS - 0.5f;
    float v = (cv * 0.5f + 0.5f) * (float)PS - 0.5f;
    u = fminf(fmaxf(u, 0.0f), (float)(PS - 1));
    v = fminf(fmaxf(v, 0.0f), (float)(PS - 1));
    const float u0f = floorf(u);
    const float v0f = floorf(v);
    const int u0 = (int)u0f;
    const int v0 = (int)v0f;
    const int u1 = min(u0 + 1, PS - 1);
    const int v1 = min(v0 + 1, PS - 1);
    const float fu = u - u0f;
    const float fv = v - v0f;

    const float* base = tpl + (size_t)PLANE * PS * PS * FD + lane;
    const float* a00 = base + ((size_t)v0 * PS + u0) * FD;
    const float* a01 = base + ((size_t)v0 * PS + u1) * FD;
    const float* a10 = base + ((size_t)v1 * PS + u0) * FD;
    const float* a11 = base + ((size_t)v1 * PS + u1) * FD;

    const float f00 = __ldg(a00);
    const float f01 = __ldg(a01);
    const float f10 = __ldg(a10);
    const float f11 = __ldg(a11);

    const float top = f00 + (f01 - f00) * fu;
    const float bot = f10 + (f11 - f10) * fu;
    const float r   = top + (bot - top) * fv;

    stg_streaming(out + (size_t)warp * (3 * FD) + PLANE * FD + lane, r);
}

extern "C" void kernel_launch(void* const* d_in, const int* in_sizes, int n_in,
                              void* d_out, int out_size)
{
    const float* coords = (const float*)d_in[0];
    const float* tpl    = (const float*)d_in[1];
    float* out          = (float*)d_out;

    const int M = in_sizes[0] / 3;           // total points = B*N
    const int warps_per_block = 256 / 32;    // 8
    const int blocks = (M + warps_per_block - 1) / warps_per_block;

    // plane 0 samples (u=x, v=y); plane 1 (u=x, v=z); plane 2 (u=z, v=y)
    tplane_pass<0, 0, 1><<<blocks, 256>>>(coords, tpl, out, M);
    tplane_pass<1, 0, 2><<<blocks, 256>>>(coords, tpl, out, M);
    tplane_pass<2, 2, 1><<<blocks, 256>>>(coords, tpl, out, M);
}

// round 7
// speedup vs baseline: 1.6336x; 1.6336x over previous
#include <cuda_runtime.h>
#include <cstdint>

// TPlanesEnc: B=4, N=131072, P=512, F=32.  M = B*N = 524288 points.
// d_in[0] = coords  [B, N, 3]   fp32
// d_in[1] = tplanes [3, P, P, F] fp32 (3 x 32 MB)
// d_out   = out     [B, N, 3*F] fp32  (201 MB streaming)
//
// R6: 3 plane passes (keeps per-pass hot texture = 32 MB, L2-resident, DRAM
// at compulsory) x 4 points per warp (MLP=16 texel loads in flight, warp
// launch/retire amortized 4x) to kill the latency-bound behavior seen in R5.

#define PS 512
#define FD 32
#define PPW 4   // points per warp

__device__ __forceinline__ void stg_streaming(float* p, float v) {
    asm volatile("st.global.cs.f32 [%0], %1;" :: "l"(p), "f"(v) : "memory");
}

template<int PLANE, int UAX, int VAX>
__global__ __launch_bounds__(256, 6)
void tplane_pass(const float* __restrict__ coords,
                 const float* __restrict__ tpl,
                 float* __restrict__ out,
                 int M)
{
    const int gtid   = blockIdx.x * blockDim.x + threadIdx.x;
    const int warp   = gtid >> 5;
    const int lane   = threadIdx.x & 31;
    const int pbase  = warp * PPW;
    if (pbase >= M) return;

    // One coalesced load of 12 contiguous coord floats for this warp's
    // 4 points; distribute via shuffle.
    float cval = 0.0f;
    if (lane < 3 * PPW) cval = __ldg(&coords[(size_t)pbase * 3 + lane]);

    const float* plbase = tpl + (size_t)PLANE * PS * PS * FD + lane;

    uint32_t off[PPW * 4];
    float fu[PPW], fv[PPW];

#pragma unroll
    for (int j = 0; j < PPW; j++) {
        const float cu = __shfl_sync(0xffffffffu, cval, j * 3 + UAX);
        const float cv = __shfl_sync(0xffffffffu, cval, j * 3 + VAX);

        float u = (cu * 0.5f + 0.5f) * (float)PS - 0.5f;
        float v = (cv * 0.5f + 0.5f) * (float)PS - 0.5f;
        u = fminf(fmaxf(u, 0.0f), (float)(PS - 1));
        v = fminf(fmaxf(v, 0.0f), (float)(PS - 1));
        const float u0f = floorf(u);
        const float v0f = floorf(v);
        const int u0 = (int)u0f;
        const int v0 = (int)v0f;
        const int u1 = min(u0 + 1, PS - 1);
        const int v1 = min(v0 + 1, PS - 1);
        fu[j] = u - u0f;
        fv[j] = v - v0f;

        off[j * 4 + 0] = ((uint32_t)v0 * PS + u0) * FD;
        off[j * 4 + 1] = ((uint32_t)v0 * PS + u1) * FD;
        off[j * 4 + 2] = ((uint32_t)v1 * PS + u0) * FD;
        off[j * 4 + 3] = ((uint32_t)v1 * PS + u1) * FD;
    }

    // Issue all 16 texel loads back-to-back (MLP=16), then interpolate.
    float tex[PPW * 4];
#pragma unroll
    for (int i = 0; i < PPW * 4; i++) tex[i] = __ldg(plbase + off[i]);

#pragma unroll
    for (int j = 0; j < PPW; j++) {
        const float f00 = tex[j * 4 + 0];
        const float f01 = tex[j * 4 + 1];
        const float f10 = tex[j * 4 + 2];
        const float f11 = tex[j * 4 + 3];
        const float top = f00 + (f01 - f00) * fu[j];
        const float bot = f10 + (f11 - f10) * fu[j];
        const float r   = top + (bot - top) * fv[j];
        stg_streaming(out + (size_t)(pbase + j) * (3 * FD) + PLANE * FD + lane, r);
    }
}

extern "C" void kernel_launch(void* const* d_in, const int* in_sizes, int n_in,
                              void* d_out, int out_size)
{
    const float* coords = (const float*)d_in[0];
    const float* tpl    = (const float*)d_in[1];
    float* out          = (float*)d_out;

    const int M = in_sizes[0] / 3;                 // total points = B*N
    const int points_per_block = (256 / 32) * PPW; // 32
    const int blocks = (M + points_per_block - 1) / points_per_block;

    // plane 0 samples (u=x, v=y); plane 1 (u=x, v=z); plane 2 (u=z, v=y)
    tplane_pass<0, 0, 1><<<blocks, 256>>>(coords, tpl, out, M);
    tplane_pass<1, 0, 2><<<blocks, 256>>>(coords, tpl, out, M);
    tplane_pass<2, 2, 1><<<blocks, 256>>>(coords, tpl, out, M);
}

// round 8
// speedup vs baseline: 1.9955x; 1.2216x over previous
#include <cuda_runtime.h>
#include <cstdint>

// TPlanesEnc: B=4, N=131072, P=512, F=32.  M = B*N = 524288 points.
// d_in[0] = coords  [B, N, 3]   fp32
// d_in[1] = tplanes [3, P, P, F] fp32
// d_out   = out     [B, N, 3*F] fp32
//
// R7: fused single pass (axis math shared across the 3 planes -> lowest
// instruction count) x 2 points per warp (coord load amortized, 24 texel
// loads in flight per warp). R6 showed the kernel family is bound by the
// ~60% issue ceiling, so minimize warp-instructions per point while keeping
// MLP high. Stores stream (.cs); output never re-read.

#define PS 512
#define FD 32
#define PPW 2   // points per warp

__device__ __forceinline__ void stg_streaming(float* p, float v) {
    asm volatile("st.global.cs.f32 [%0], %1;" :: "l"(p), "f"(v) : "memory");
}

__global__ __launch_bounds__(256)
void tplanes_kernel(const float* __restrict__ coords,
                    const float* __restrict__ tpl,
                    float* __restrict__ out,
                    int M)
{
    const int gtid  = blockIdx.x * blockDim.x + threadIdx.x;
    const int warp  = gtid >> 5;
    const int lane  = threadIdx.x & 31;
    const int pbase = warp * PPW;
    if (pbase >= M) return;

    // One coalesced coord fetch for both points (6 floats), spread by shuffle.
    float cval = 0.0f;
    if (lane < 3 * PPW) cval = __ldg(&coords[(size_t)pbase * 3 + lane]);

    const float* tbl = tpl + lane;  // lane = channel

    // plane 0 samples (u=x, v=y); plane 1 (u=x, v=z); plane 2 (u=z, v=y)
    uint32_t off[PPW * 12];
    float fu[PPW * 3], fv[PPW * 3];

#pragma unroll
    for (int j = 0; j < PPW; j++) {
        int i0[3], i1[3];
        float fr[3];
#pragma unroll
        for (int a = 0; a < 3; a++) {
            const float c = __shfl_sync(0xffffffffu, cval, j * 3 + a);
            float x = (c * 0.5f + 0.5f) * (float)PS - 0.5f;
            x = fminf(fmaxf(x, 0.0f), (float)(PS - 1));
            const float x0f = floorf(x);
            const int xi0 = (int)x0f;
            i0[a] = xi0;
            i1[a] = min(xi0 + 1, PS - 1);
            fr[a] = x - x0f;
        }

        const int uax[3] = {0, 0, 2};
        const int vax[3] = {1, 2, 1};
#pragma unroll
        for (int p = 0; p < 3; p++) {
            const uint32_t pb = (uint32_t)p * PS * PS * FD;
            const uint32_t r0 = pb + (uint32_t)i0[vax[p]] * (PS * FD);
            const uint32_t r1 = pb + (uint32_t)i1[vax[p]] * (PS * FD);
            const uint32_t c0 = (uint32_t)i0[uax[p]] * FD;
            const uint32_t c1 = (uint32_t)i1[uax[p]] * FD;
            off[j * 12 + p * 4 + 0] = r0 + c0;
            off[j * 12 + p * 4 + 1] = r0 + c1;
            off[j * 12 + p * 4 + 2] = r1 + c0;
            off[j * 12 + p * 4 + 3] = r1 + c1;
            fu[j * 3 + p] = fr[uax[p]];
            fv[j * 3 + p] = fr[vax[p]];
        }
    }

    // Issue all texel loads back-to-back (MLP = 24 per warp).
    float tex[PPW * 12];
#pragma unroll
    for (int i = 0; i < PPW * 12; i++) tex[i] = __ldg(tbl + off[i]);

#pragma unroll
    for (int j = 0; j < PPW; j++) {
        float* op = out + (size_t)(pbase + j) * (3 * FD) + lane;
#pragma unroll
        for (int p = 0; p < 3; p++) {
            const float f00 = tex[j * 12 + p * 4 + 0];
            const float f01 = tex[j * 12 + p * 4 + 1];
            const float f10 = tex[j * 12 + p * 4 + 2];
            const float f11 = tex[j * 12 + p * 4 + 3];
            const float x_ = fu[j * 3 + p];
            const float y_ = fv[j * 3 + p];
            const float top = f00 + (f01 - f00) * x_;
            const float bot = f10 + (f11 - f10) * x_;
            stg_streaming(op + p * FD, top + (bot - top) * y_);
        }
    }
}

extern "C" void kernel_launch(void* const* d_in, const int* in_sizes, int n_in,
                              void* d_out, int out_size)
{
    const float* coords = (const float*)d_in[0];
    const float* tpl    = (const float*)d_in[1];
    float* out          = (float*)d_out;

    const int M = in_sizes[0] / 3;                  // total points = B*N
    const int points_per_block = (256 / 32) * PPW;  // 16
    const int blocks = (M + points_per_block - 1) / points_per_block;
    tplanes_kernel<<<blocks, 256>>>(coords, tpl, out, M);
}